// round 15
// baseline (speedup 1.0000x reference)
#include <cuda_runtime.h>
#include <cuda_fp16.h>
#include <cstdint>

// Hopf oscillator CPG step, reformulated:
//   sin(psi_j - psi_i - phi_ij) = (s_j c_i - c_j s_i)cosφ - (c_j c_i + s_j s_i)sinφ
// A_ij = w_zd cosφ_zd, B_ij = w_zd sinφ_zd, x_j = r_j s_j, y_j = r_j c_j:
//   coupling_i = c_i*(A x - B y)_i - s_i*(A y + B x)_i
// R15 = R14 (19.0us, best) + surgical latency hiding:
//  * ALL 24 LDGs hoisted into one MLP=24 burst; rd/rdd computed+stored
//    immediately so rd[] dies at once (only psi/rr[4..7] stay live through
//    quad-0's inner loop: ~+8 regs, NOT R13's +40 -> no spill)
//  * pre-STS __syncwarp dropped (sXY is quad-indexed, buffers disjoint)
//  * launch_bounds(256,4): 64-reg cap; occ 40% proven neutral (R11)

#define PI2F 6.28318530717958647692f

__device__ uint2 gABBA[1024];   // [j*32 + i] = {half2{A,B}, half2{B,A}} (pre-transposed)
__device__ float gTPV[32];      // 2*pi*V_MAX*sigmoid(v)
__device__ float gBA[32];       // B_MAX*sigmoid(b)
__device__ float gCA[32];       // C_MAX*sigmoid(c)

__device__ __forceinline__ float fsigmoid(float x) {
    return 1.0f / (1.0f + __expf(-x));
}

__global__ void prep_kernel(const float* __restrict__ v, const float* __restrict__ b,
                            const float* __restrict__ c, const float* __restrict__ w,
                            const float* __restrict__ phi) {
    int m = blockIdx.x * 128 + threadIdx.x;   // 0..1023, m = i*32 + j
    float A = 0.0f, Bv = 0.0f;
    if (m % 33 != 0) {              // zero-diag: diagonal iff m % 33 == 0
        int kk = m / 33;            // 0..30
        int jj = m % 33 - 1;        // 0..31
        float wa = fsigmoid(w[kk * 32 + jj]);           // W_MAX = 1
        float pa = PI2F * fsigmoid(phi[kk * 32 + jj]);  // PHI_MAX = 2*pi
        float sp, cp;
        __sincosf(pa, &sp, &cp);
        A  = wa * cp;
        Bv = wa * sp;
    }
    __half2 ab = __floats2half2_rn(A, Bv);
    __half2 ba = __floats2half2_rn(Bv, A);
    gABBA[(m & 31) * 32 + (m >> 5)] =
        make_uint2(*reinterpret_cast<uint32_t*>(&ab), *reinterpret_cast<uint32_t*>(&ba));
    if (m < 32) {
        gTPV[m] = (PI2F * 5.0f) * fsigmoid(v[m]);
        gBA[m]  = 2.0f  * fsigmoid(b[m]);
        gCA[m]  = 10.0f * fsigmoid(c[m]);
    }
}

// ---------------- hot kernel: full 64-row tiles only, no guards ----------------
__global__ __launch_bounds__(256, 4)
void hopf_kernel(const float* __restrict__ in, float* __restrict__ out) {
    const int tid  = threadIdx.x;
    const int lane = tid & 31;          // oscillator index i
    const int wib  = tid >> 5;          // warp in block (0..7)

    __shared__ uint2 sABBA[1024];       // [j*32 + i] -> LDS.64
    __shared__ uint4 sXY[8][2][32];     // [warp][quad][j] = half2{x,y} rows 0..3

    // coalesced L2->smem copy of the prebuilt matrix (8KB, 2 float4/thread)
    {
        const float4* src = reinterpret_cast<const float4*>(gABBA);
        float4*       dst = reinterpret_cast<float4*>(sABBA);
        dst[tid]       = src[tid];
        dst[tid + 256] = src[tid + 256];
    }

    const float tpv = gTPV[lane];
    const float ba  = gBA[lane];
    const float ca  = gCA[lane];

    __syncthreads();

    const int rowBase = (blockIdx.x * 8 + wib) * 8;   // 8 rows per warp

    // ---- one LDG burst for all 8 rows (MLP=24); rd dies immediately ----
    float psi[8], rr[8];
    {
        float rd[8];
        #pragma unroll
        for (int t = 0; t < 8; t++) {
            const float* rp = in + (size_t)(rowBase + t) * 96;
            psi[t] = rp[lane];
            rr[t]  = rp[32 + lane];
            rd[t]  = rp[64 + lane];
        }
        #pragma unroll
        for (int t = 0; t < 8; t++) {
            float rdd = ca * (0.25f * ca * (ba - rr[t]) - rd[t]);
            float* op = out + (size_t)(rowBase + t) * 96;
            op[32 + lane] = rd[t];
            op[64 + lane] = rdd;
        }
    }

    #pragma unroll
    for (int q = 0; q < 2; q++) {
        float sv[4], cv[4];
        uint4 xy;                        // 4 rows of half2{x,y}, built in regs

        #pragma unroll
        for (int t = 0; t < 4; t++) {
            const int tt = q * 4 + t;
            __sincosf(psi[tt], &sv[t], &cv[t]);
            reinterpret_cast<__half2*>(&xy)[t] =
                __floats2half2_rn(rr[tt] * sv[t], rr[tt] * cv[t]);   // {x,y}
        }

        sXY[wib][q][lane] = xy;          // 1 STS.128 (disjoint buffer per quad)
        __syncwarp();                    // make lanes' stores visible

        // split half2 accumulators: [t] over 4 rows; 0 = j<16, 1 = j>=16
        __half2 z = __floats2half2_rn(0.0f, 0.0f);
        __half2 aP0[4] = {z,z,z,z}, aP1[4] = {z,z,z,z};
        __half2 aQ0[4] = {z,z,z,z}, aQ1[4] = {z,z,z,z};

        #pragma unroll
        for (int j = 0; j < 16; j++) {
            uint2 m = sABBA[j * 32 + lane];              // LDS.64 {AB, BA}
            __half2 ab  = *reinterpret_cast<__half2*>(&m.x);
            __half2 ba2 = *reinterpret_cast<__half2*>(&m.y);
            uint4 pxy = sXY[wib][q][j];                  // broadcast LDS.128
            const __half2* hx = reinterpret_cast<const __half2*>(&pxy);
            #pragma unroll
            for (int t = 0; t < 4; t++) {
                aP0[t] = __hfma2(ab,  hx[t], aP0[t]);    // {ΣAx, ΣBy}
                aQ0[t] = __hfma2(ba2, hx[t], aQ0[t]);    // {ΣBx, ΣAy}
            }
        }
        #pragma unroll
        for (int j = 16; j < 32; j++) {
            uint2 m = sABBA[j * 32 + lane];
            __half2 ab  = *reinterpret_cast<__half2*>(&m.x);
            __half2 ba2 = *reinterpret_cast<__half2*>(&m.y);
            uint4 pxy = sXY[wib][q][j];
            const __half2* hx = reinterpret_cast<const __half2*>(&pxy);
            #pragma unroll
            for (int t = 0; t < 4; t++) {
                aP1[t] = __hfma2(ab,  hx[t], aP1[t]);
                aQ1[t] = __hfma2(ba2, hx[t], aQ1[t]);
            }
        }

        #pragma unroll
        for (int t = 0; t < 4; t++) {
            float2 p0 = __half22float2(aP0[t]);
            float2 p1 = __half22float2(aP1[t]);
            float2 q0 = __half22float2(aQ0[t]);
            float2 q1 = __half22float2(aQ1[t]);
            float P = (p0.x + p1.x) - (p0.y + p1.y);     // ΣAx - ΣBy
            float Q = (q0.x + q1.x) + (q0.y + q1.y);     // ΣBx + ΣAy
            out[(size_t)(rowBase + q * 4 + t) * 96 + lane] =
                tpv + cv[t] * P - sv[t] * Q;
        }
    }
}

// ---------------- guarded tail kernel (remainder rows; unused at 65536) --------
__global__ void hopf_tail(const float* __restrict__ in, float* __restrict__ out,
                          int rowStart, int nrows) {
    const int tid  = threadIdx.x;
    const int lane = tid & 31;
    const int wib  = tid >> 5;

    __shared__ uint2 sABBA[1024];
    __shared__ uint4 sXY[8][2][32];

    {
        const float4* src = reinterpret_cast<const float4*>(gABBA);
        float4*       dst = reinterpret_cast<float4*>(sABBA);
        dst[tid]       = src[tid];
        dst[tid + 256] = src[tid + 256];
    }
    const float tpv = gTPV[lane];
    const float ba  = gBA[lane];
    const float ca  = gCA[lane];
    __syncthreads();

    const int rowBase = rowStart + wib * 8;

    #pragma unroll
    for (int q = 0; q < 2; q++) {
        const int r0 = rowBase + q * 4;
        float sv[4], cv[4];
        uint4 xy;

        #pragma unroll
        for (int t = 0; t < 4; t++) {
            const int row = r0 + t;
            float psi = 0.0f, rr = 0.0f, rd = 0.0f;
            if (row < nrows) {
                const float* rp = in + (size_t)row * 96;
                psi = rp[lane];  rr = rp[32 + lane];  rd = rp[64 + lane];
            }
            __sincosf(psi, &sv[t], &cv[t]);
            reinterpret_cast<__half2*>(&xy)[t] =
                __floats2half2_rn(rr * sv[t], rr * cv[t]);
            if (row < nrows) {
                float rdd = ca * (0.25f * ca * (ba - rr) - rd);
                float* op = out + (size_t)row * 96;
                op[32 + lane] = rd;
                op[64 + lane] = rdd;
            }
        }

        sXY[wib][q][lane] = xy;
        __syncwarp();

        __half2 z = __floats2half2_rn(0.0f, 0.0f);
        __half2 aP0[4] = {z,z,z,z}, aP1[4] = {z,z,z,z};
        __half2 aQ0[4] = {z,z,z,z}, aQ1[4] = {z,z,z,z};

        #pragma unroll
        for (int j = 0; j < 16; j++) {
            uint2 m = sABBA[j * 32 + lane];
            __half2 ab  = *reinterpret_cast<__half2*>(&m.x);
            __half2 ba2 = *reinterpret_cast<__half2*>(&m.y);
            uint4 pxy = sXY[wib][q][j];
            const __half2* hx = reinterpret_cast<const __half2*>(&pxy);
            #pragma unroll
            for (int t = 0; t < 4; t++) {
                aP0[t] = __hfma2(ab,  hx[t], aP0[t]);
                aQ0[t] = __hfma2(ba2, hx[t], aQ0[t]);
            }
        }
        #pragma unroll
        for (int j = 16; j < 32; j++) {
            uint2 m = sABBA[j * 32 + lane];
            __half2 ab  = *reinterpret_cast<__half2*>(&m.x);
            __half2 ba2 = *reinterpret_cast<__half2*>(&m.y);
            uint4 pxy = sXY[wib][q][j];
            const __half2* hx = reinterpret_cast<const __half2*>(&pxy);
            #pragma unroll
            for (int t = 0; t < 4; t++) {
                aP1[t] = __hfma2(ab,  hx[t], aP1[t]);
                aQ1[t] = __hfma2(ba2, hx[t], aQ1[t]);
            }
        }

        #pragma unroll
        for (int t = 0; t < 4; t++) {
            const int row = r0 + t;
            if (row < nrows) {
                float2 p0 = __half22float2(aP0[t]);
                float2 p1 = __half22float2(aP1[t]);
                float2 q0 = __half22float2(aQ0[t]);
                float2 q1 = __half22float2(aQ1[t]);
                float P = (p0.x + p1.x) - (p0.y + p1.y);
                float Q = (q0.x + q1.x) + (q0.y + q1.y);
                out[(size_t)row * 96 + lane] = tpv + cv[t] * P - sv[t] * Q;
            }
        }
    }
}

extern "C" void kernel_launch(void* const* d_in, const int* in_sizes, int n_in,
                              void* d_out, int out_size) {
    const float* states = (const float*)d_in[0];
    const float* v      = (const float*)d_in[1];
    const float* b      = (const float*)d_in[2];
    const float* c      = (const float*)d_in[3];
    const float* w      = (const float*)d_in[4];
    const float* phi    = (const float*)d_in[5];
    float* out = (float*)d_out;

    const int nrows = in_sizes[0] / 96;         // 65536
    prep_kernel<<<8, 128>>>(v, b, c, w, phi);

    const int fullBlocks = nrows / 64;          // 64 rows per 256-thread block
    if (fullBlocks > 0)
        hopf_kernel<<<fullBlocks, 256>>>(states, out);

    const int covered = fullBlocks * 64;
    if (covered < nrows)
        hopf_tail<<<1, 256>>>(states, out, covered, nrows);
}

// round 16
// speedup vs baseline: 1.1556x; 1.1556x over previous
#include <cuda_runtime.h>
#include <cuda_fp16.h>
#include <cstdint>

// ============================================================================
// Hopf CPG step: coupling via fp16 HMMA (mma.sync.m16n8k16, baseline PTX).
//   sin(psi_j-psi_i-phi) = (s_j c_i - c_j s_i)cosφ - (c_j c_i + s_j s_i)sinφ
//   A=w_zd cosφ, B=w_zd sinφ, x=r·s, y=r·c
//   GEMM: Z[row][2j,2j+1]={x_j,y_j};  W[2j][i]=A[i][j], W[2j+1][i]=-B[i][j]
//         (n=i<32: P),  W[2j][32+i]=B[i][j], W[2j+1][32+i]=A[i][j]  (n=32+i: Q)
//   psi_dot_i = tpv_i + c_i·P_i - s_i·Q_i    (fp32 accumulators in the MMA)
// W fragments PRE-PACKED by prep kernel in exact m16n8k16 B-fragment order ->
// main-kernel b-load is one lane-consecutive LDS.64 per mma. A-frags read from
// padded smem (stride 36 words: bank = 4r+j, conflict-free). 128-thr CTAs,
// 64 rows/CTA, grid 1024, 7 CTAs/SM (single wave).
// ============================================================================

#define PI2F 6.28318530717958647692f

__device__ uint2 gBfrag[1024];  // [ntile(8)][kstep(4)][lane(32)] = {b0,b1}
__device__ uint2 gABBA[1024];   // tail-kernel matrix (R14 layout)
__device__ float gTPV[32];
__device__ float gBA[32];
__device__ float gCA[32];

__device__ __forceinline__ float fsigmoid(float x) {
    return 1.0f / (1.0f + __expf(-x));
}

#define MMA_F16(d, a0,a1,a2,a3, b0,b1) \
    asm volatile("mma.sync.aligned.m16n8k16.row.col.f32.f16.f16.f32 " \
        "{%0,%1,%2,%3}, {%4,%5,%6,%7}, {%8,%9}, {%0,%1,%2,%3};" \
        : "+f"((d)[0]), "+f"((d)[1]), "+f"((d)[2]), "+f"((d)[3]) \
        : "r"(a0), "r"(a1), "r"(a2), "r"(a3), "r"(b0), "r"(b1))

__global__ void prep_kernel(const float* __restrict__ v, const float* __restrict__ b,
                            const float* __restrict__ c, const float* __restrict__ w,
                            const float* __restrict__ phi) {
    __shared__ float sA[1024], sB[1024];      // [i*32 + j]
    const int tid = threadIdx.x;              // 128 threads, 8 blocks

    #pragma unroll
    for (int e = 0; e < 8; e++) {
        int m = e * 128 + tid;                // i*32 + j
        float A = 0.0f, Bv = 0.0f;
        if (m % 33 != 0) {                    // zero-diag
            int kk = m / 33, jj = m % 33 - 1;
            float wa = fsigmoid(w[kk * 32 + jj]);            // W_MAX=1
            float pa = PI2F * fsigmoid(phi[kk * 32 + jj]);   // PHI_MAX=2pi
            float sp, cp;
            __sincosf(pa, &sp, &cp);
            A = wa * cp;  Bv = wa * sp;
        }
        sA[m] = A;  sB[m] = Bv;
    }
    __syncthreads();

    const int m = blockIdx.x * 128 + tid;     // 0..1023: this block's slice
    // --- m16n8k16 B-fragment packing ---
    {
        int ntile = m >> 7, ks = (m >> 5) & 3, ln = m & 31;
        int g = ln >> 2, tig = ln & 3;
        int n  = ntile * 8 + g;
        int j0 = ks * 8 + tig, j1 = j0 + 4;
        float b0x, b0y, b1x, b1y;
        if (n < 32) {            // P block: {A, -B}
            b0x = sA[n * 32 + j0];  b0y = -sB[n * 32 + j0];
            b1x = sA[n * 32 + j1];  b1y = -sB[n * 32 + j1];
        } else {                 // Q block: {B, A}
            int i = n - 32;
            b0x = sB[i * 32 + j0];  b0y = sA[i * 32 + j0];
            b1x = sB[i * 32 + j1];  b1y = sA[i * 32 + j1];
        }
        __half2 h0 = __floats2half2_rn(b0x, b0y);
        __half2 h1 = __floats2half2_rn(b1x, b1y);
        gBfrag[m] = make_uint2(*reinterpret_cast<uint32_t*>(&h0),
                               *reinterpret_cast<uint32_t*>(&h1));
    }
    // --- tail-kernel matrix (R14 layout) ---
    {
        __half2 ab = __floats2half2_rn(sA[m], sB[m]);
        __half2 ba = __floats2half2_rn(sB[m], sA[m]);
        gABBA[(m & 31) * 32 + (m >> 5)] =
            make_uint2(*reinterpret_cast<uint32_t*>(&ab),
                       *reinterpret_cast<uint32_t*>(&ba));
    }
    if (blockIdx.x == 0 && m < 32) {
        gTPV[m] = (PI2F * 5.0f) * fsigmoid(v[m]);
        gBA[m]  = 2.0f  * fsigmoid(b[m]);
        gCA[m]  = 10.0f * fsigmoid(c[m]);
    }
}

// ---------------- hot kernel: 64 full rows per 128-thread CTA -----------------
#define XS 36   // padded row stride (words): bank = (36r + j) % 32 = (4r+j) % 32

__global__ __launch_bounds__(128, 7)
void hopf_kernel(const float* __restrict__ in, float* __restrict__ out) {
    __shared__ uint2    sBf[1024];       // B fragments (8KB)
    __shared__ uint32_t sXY[64 * XS];    // [row][j] half2{x,y}
    __shared__ uint32_t sSC[64 * XS];    // [row][i] half2{c,s}
    __shared__ float    sTPV[32];

    const int tid  = threadIdx.x;
    const int lane = tid & 31;
    const int wid  = tid >> 5;           // 0..3
    const int warpRow = wid * 16;
    const size_t rowBase = (size_t)blockIdx.x * 64;

    // coalesced copy of prebuilt fragments (8KB = 512 float4, 4/thread)
    {
        const float4* src = reinterpret_cast<const float4*>(gBfrag);
        float4*       dst = reinterpret_cast<float4*>(sBf);
        #pragma unroll
        for (int e = 0; e < 4; e++) dst[tid + e * 128] = src[tid + e * 128];
    }
    if (tid < 32) sTPV[tid] = gTPV[tid];

    const float ba = gBA[lane];
    const float ca = gCA[lane];

    // ---- prologue: 16 rows/warp in two 8-row batches (lane = oscillator) ----
    #pragma unroll
    for (int batch = 0; batch < 2; batch++) {
        float psi[8], rr[8], rd[8];
        #pragma unroll
        for (int t = 0; t < 8; t++) {
            int r = warpRow + batch * 8 + t;
            const float* rp = in + (rowBase + r) * 96;
            psi[t] = rp[lane];
            rr[t]  = rp[32 + lane];
            rd[t]  = rp[64 + lane];
        }
        #pragma unroll
        for (int t = 0; t < 8; t++) {
            int r = warpRow + batch * 8 + t;
            float sv, cv;
            __sincosf(psi[t], &sv, &cv);
            __half2 hxy = __floats2half2_rn(rr[t] * sv, rr[t] * cv);
            __half2 hcs = __floats2half2_rn(cv, sv);
            sXY[r * XS + lane] = *reinterpret_cast<uint32_t*>(&hxy);
            sSC[r * XS + lane] = *reinterpret_cast<uint32_t*>(&hcs);
            float rdd = ca * (0.25f * ca * (ba - rr[t]) - rd[t]);
            float* op = out + (rowBase + r) * 96;
            op[32 + lane] = rd[t];
            op[64 + lane] = rdd;
        }
    }
    __syncthreads();    // sBf visible to all; sXY/sSC (per-warp) also covered

    // ---- MMA: warp owns 16 rows; accP = n-tiles 0..3 (P), accQ = 4..7 (Q) ----
    float accP[4][4] = {}, accQ[4][4] = {};
    const int g   = lane >> 2;
    const int tig = lane & 3;
    const int ar0 = warpRow + g;

    #pragma unroll
    for (int ks = 0; ks < 4; ks++) {
        int hj = ks * 8 + tig;
        uint32_t a0 = sXY[ar0 * XS + hj];
        uint32_t a1 = sXY[(ar0 + 8) * XS + hj];
        uint32_t a2 = sXY[ar0 * XS + hj + 4];
        uint32_t a3 = sXY[(ar0 + 8) * XS + hj + 4];
        #pragma unroll
        for (int nt = 0; nt < 4; nt++) {
            uint2 bP = sBf[nt * 128 + ks * 32 + lane];          // LDS.64
            MMA_F16(accP[nt], a0, a1, a2, a3, bP.x, bP.y);
            uint2 bQ = sBf[(nt + 4) * 128 + ks * 32 + lane];
            MMA_F16(accQ[nt], a0, a1, a2, a3, bQ.x, bQ.y);
        }
    }

    // ---- epilogue: thread owns rows (ar0, ar0+8) x cols (i0, i0+1)/ntile ----
    #pragma unroll
    for (int nt = 0; nt < 4; nt++) {
        int i0 = nt * 8 + tig * 2;
        float2 tp = *reinterpret_cast<const float2*>(&sTPV[i0]);
        #pragma unroll
        for (int rs = 0; rs < 2; rs++) {
            int r = ar0 + rs * 8;
            uint2 scu = *reinterpret_cast<const uint2*>(&sSC[r * XS + i0]);
            __half2 h0 = *reinterpret_cast<__half2*>(&scu.x);   // {c,s} col i0
            __half2 h1 = *reinterpret_cast<__half2*>(&scu.y);   // {c,s} col i0+1
            float c0 = __low2float(h0), s0 = __high2float(h0);
            float c1 = __low2float(h1), s1 = __high2float(h1);
            float P0 = accP[nt][rs * 2], P1 = accP[nt][rs * 2 + 1];
            float Q0 = accQ[nt][rs * 2], Q1 = accQ[nt][rs * 2 + 1];
            float2 pd;
            pd.x = tp.x + c0 * P0 - s0 * Q0;
            pd.y = tp.y + c1 * P1 - s1 * Q1;
            *reinterpret_cast<float2*>(&out[(rowBase + r) * 96 + i0]) = pd;
        }
    }
}

// ---------------- guarded tail kernel (R14 path; unused at 65536) -------------
__global__ void hopf_tail(const float* __restrict__ in, float* __restrict__ out,
                          int rowStart, int nrows) {
    const int tid  = threadIdx.x;
    const int lane = tid & 31;
    const int wib  = tid >> 5;

    __shared__ uint2 sABBA[1024];
    __shared__ uint4 sXYt[8][2][32];

    {
        const float4* src = reinterpret_cast<const float4*>(gABBA);
        float4*       dst = reinterpret_cast<float4*>(sABBA);
        dst[tid]       = src[tid];
        dst[tid + 256] = src[tid + 256];
    }
    const float tpv = gTPV[lane];
    const float ba  = gBA[lane];
    const float ca  = gCA[lane];
    __syncthreads();

    const int rowBase = rowStart + wib * 8;

    #pragma unroll
    for (int q = 0; q < 2; q++) {
        const int r0 = rowBase + q * 4;
        float sv[4], cv[4];
        uint4 xy;

        #pragma unroll
        for (int t = 0; t < 4; t++) {
            const int row = r0 + t;
            float psi = 0.0f, rr = 0.0f, rd = 0.0f;
            if (row < nrows) {
                const float* rp = in + (size_t)row * 96;
                psi = rp[lane];  rr = rp[32 + lane];  rd = rp[64 + lane];
            }
            __sincosf(psi, &sv[t], &cv[t]);
            reinterpret_cast<__half2*>(&xy)[t] =
                __floats2half2_rn(rr * sv[t], rr * cv[t]);
            if (row < nrows) {
                float rdd = ca * (0.25f * ca * (ba - rr) - rd);
                float* op = out + (size_t)row * 96;
                op[32 + lane] = rd;
                op[64 + lane] = rdd;
            }
        }

        sXYt[wib][q][lane] = xy;
        __syncwarp();

        __half2 z = __floats2half2_rn(0.0f, 0.0f);
        __half2 aP0[4] = {z,z,z,z}, aP1[4] = {z,z,z,z};
        __half2 aQ0[4] = {z,z,z,z}, aQ1[4] = {z,z,z,z};

        #pragma unroll
        for (int j = 0; j < 16; j++) {
            uint2 m = sABBA[j * 32 + lane];
            __half2 ab  = *reinterpret_cast<__half2*>(&m.x);
            __half2 ba2 = *reinterpret_cast<__half2*>(&m.y);
            uint4 pxy = sXYt[wib][q][j];
            const __half2* hx = reinterpret_cast<const __half2*>(&pxy);
            #pragma unroll
            for (int t = 0; t < 4; t++) {
                aP0[t] = __hfma2(ab,  hx[t], aP0[t]);
                aQ0[t] = __hfma2(ba2, hx[t], aQ0[t]);
            }
        }
        #pragma unroll
        for (int j = 16; j < 32; j++) {
            uint2 m = sABBA[j * 32 + lane];
            __half2 ab  = *reinterpret_cast<__half2*>(&m.x);
            __half2 ba2 = *reinterpret_cast<__half2*>(&m.y);
            uint4 pxy = sXYt[wib][q][j];
            const __half2* hx = reinterpret_cast<const __half2*>(&pxy);
            #pragma unroll
            for (int t = 0; t < 4; t++) {
                aP1[t] = __hfma2(ab,  hx[t], aP1[t]);
                aQ1[t] = __hfma2(ba2, hx[t], aQ1[t]);
            }
        }

        #pragma unroll
        for (int t = 0; t < 4; t++) {
            const int row = r0 + t;
            if (row < nrows) {
                float2 p0 = __half22float2(aP0[t]);
                float2 p1 = __half22float2(aP1[t]);
                float2 q0 = __half22float2(aQ0[t]);
                float2 q1 = __half22float2(aQ1[t]);
                float P = (p0.x + p1.x) - (p0.y + p1.y);
                float Q = (q0.x + q1.x) + (q0.y + q1.y);
                out[(size_t)row * 96 + lane] = tpv + cv[t] * P - sv[t] * Q;
            }
        }
    }
}

extern "C" void kernel_launch(void* const* d_in, const int* in_sizes, int n_in,
                              void* d_out, int out_size) {
    const float* states = (const float*)d_in[0];
    const float* v      = (const float*)d_in[1];
    const float* b      = (const float*)d_in[2];
    const float* c      = (const float*)d_in[3];
    const float* w      = (const float*)d_in[4];
    const float* phi    = (const float*)d_in[5];
    float* out = (float*)d_out;

    const int nrows = in_sizes[0] / 96;         // 65536
    prep_kernel<<<8, 128>>>(v, b, c, w, phi);

    const int fullBlocks = nrows / 64;          // 64 rows per 128-thread CTA
    if (fullBlocks > 0)
        hopf_kernel<<<fullBlocks, 128>>>(states, out);

    const int covered = fullBlocks * 64;
    if (covered < nrows)
        hopf_tail<<<1, 256>>>(states, out, covered, nrows);
}

// round 17
// speedup vs baseline: 1.2583x; 1.0888x over previous
#include <cuda_runtime.h>
#include <cuda_fp16.h>
#include <cstdint>

// ============================================================================
// Hopf CPG step: coupling via fp16 HMMA (mma.sync.m16n8k16, baseline PTX).
//   sin(psi_j-psi_i-phi) = (s_j c_i - c_j s_i)cosφ - (c_j c_i + s_j s_i)sinφ
//   A=w_zd cosφ, B=w_zd sinφ, x=r·s, y=r·c
//   GEMM: Z[row][2j,2j+1]={x_j,y_j};  W[2j][i]=A[i][j], W[2j+1][i]=-B[i][j]
//         (n=i<32: P),  W[2j][32+i]=B[i][j], W[2j+1][32+i]=A[i][j]  (n=32+i: Q)
//   psi_dot_i = tpv_i + c_i·P_i - s_i·Q_i    (fp32 accumulators in the MMA)
// R17 = R16 (16.9us, best):
//  * prep collapsed to ONE 1024-thread block, one entry per thread (R16 ran the
//    full matrix build redundantly in all 8 blocks)
//  * prologue LDG bursts 8 rows -> 4 rows (MLP_p1 24->12) to cut the one-wave
//    cross-CTA L1tex-queue straggler spread (B300 spr_max model)
// ============================================================================

#define PI2F 6.28318530717958647692f

__device__ uint2 gBfrag[1024];  // [ntile(8)][kstep(4)][lane(32)] = {b0,b1}
__device__ uint2 gABBA[1024];   // tail-kernel matrix (R14 layout)
__device__ float gTPV[32];
__device__ float gBA[32];
__device__ float gCA[32];

__device__ __forceinline__ float fsigmoid(float x) {
    return 1.0f / (1.0f + __expf(-x));
}

#define MMA_F16(d, a0,a1,a2,a3, b0,b1) \
    asm volatile("mma.sync.aligned.m16n8k16.row.col.f32.f16.f16.f32 " \
        "{%0,%1,%2,%3}, {%4,%5,%6,%7}, {%8,%9}, {%0,%1,%2,%3};" \
        : "+f"((d)[0]), "+f"((d)[1]), "+f"((d)[2]), "+f"((d)[3]) \
        : "r"(a0), "r"(a1), "r"(a2), "r"(a3), "r"(b0), "r"(b1))

// One block, 1024 threads: each thread computes its ONE matrix entry, then
// packs its ONE fragment slot from smem. No redundant work.
__global__ __launch_bounds__(1024)
void prep_kernel(const float* __restrict__ v, const float* __restrict__ b,
                 const float* __restrict__ c, const float* __restrict__ w,
                 const float* __restrict__ phi) {
    __shared__ float sA[1024], sB[1024];      // [i*32 + j]
    const int m = threadIdx.x;                // 0..1023 = i*32 + j

    {
        float A = 0.0f, Bv = 0.0f;
        if (m % 33 != 0) {                    // zero-diag
            int kk = m / 33, jj = m % 33 - 1;
            float wa = fsigmoid(w[kk * 32 + jj]);            // W_MAX=1
            float pa = PI2F * fsigmoid(phi[kk * 32 + jj]);   // PHI_MAX=2pi
            float sp, cp;
            __sincosf(pa, &sp, &cp);
            A = wa * cp;  Bv = wa * sp;
        }
        sA[m] = A;  sB[m] = Bv;
    }
    __syncthreads();

    // --- m16n8k16 B-fragment packing (one slot per thread) ---
    {
        int ntile = m >> 7, ks = (m >> 5) & 3, ln = m & 31;
        int g = ln >> 2, tig = ln & 3;
        int n  = ntile * 8 + g;
        int j0 = ks * 8 + tig, j1 = j0 + 4;
        float b0x, b0y, b1x, b1y;
        if (n < 32) {            // P block: {A, -B}
            b0x = sA[n * 32 + j0];  b0y = -sB[n * 32 + j0];
            b1x = sA[n * 32 + j1];  b1y = -sB[n * 32 + j1];
        } else {                 // Q block: {B, A}
            int i = n - 32;
            b0x = sB[i * 32 + j0];  b0y = sA[i * 32 + j0];
            b1x = sB[i * 32 + j1];  b1y = sA[i * 32 + j1];
        }
        __half2 h0 = __floats2half2_rn(b0x, b0y);
        __half2 h1 = __floats2half2_rn(b1x, b1y);
        gBfrag[m] = make_uint2(*reinterpret_cast<uint32_t*>(&h0),
                               *reinterpret_cast<uint32_t*>(&h1));
    }
    // --- tail-kernel matrix (R14 layout) ---
    {
        __half2 ab = __floats2half2_rn(sA[m], sB[m]);
        __half2 ba = __floats2half2_rn(sB[m], sA[m]);
        gABBA[(m & 31) * 32 + (m >> 5)] =
            make_uint2(*reinterpret_cast<uint32_t*>(&ab),
                       *reinterpret_cast<uint32_t*>(&ba));
    }
    if (m < 32) {
        gTPV[m] = (PI2F * 5.0f) * fsigmoid(v[m]);
        gBA[m]  = 2.0f  * fsigmoid(b[m]);
        gCA[m]  = 10.0f * fsigmoid(c[m]);
    }
}

// ---------------- hot kernel: 64 full rows per 128-thread CTA -----------------
#define XS 36   // padded row stride (words): bank = (36r + j) % 32 = (4r+j) % 32

__global__ __launch_bounds__(128, 7)
void hopf_kernel(const float* __restrict__ in, float* __restrict__ out) {
    __shared__ uint2    sBf[1024];       // B fragments (8KB)
    __shared__ uint32_t sXY[64 * XS];    // [row][j] half2{x,y}
    __shared__ uint32_t sSC[64 * XS];    // [row][i] half2{c,s}
    __shared__ float    sTPV[32];

    const int tid  = threadIdx.x;
    const int lane = tid & 31;
    const int wid  = tid >> 5;           // 0..3
    const int warpRow = wid * 16;
    const size_t rowBase = (size_t)blockIdx.x * 64;

    // coalesced copy of prebuilt fragments (8KB = 512 float4, 4/thread)
    {
        const float4* src = reinterpret_cast<const float4*>(gBfrag);
        float4*       dst = reinterpret_cast<float4*>(sBf);
        #pragma unroll
        for (int e = 0; e < 4; e++) dst[tid + e * 128] = src[tid + e * 128];
    }
    if (tid < 32) sTPV[tid] = gTPV[tid];

    const float ba = gBA[lane];
    const float ca = gCA[lane];

    // ---- prologue: 16 rows/warp in four 4-row batches (MLP_p1 = 12) ----
    #pragma unroll
    for (int batch = 0; batch < 4; batch++) {
        float psi[4], rr[4], rd[4];
        #pragma unroll
        for (int t = 0; t < 4; t++) {
            int r = warpRow + batch * 4 + t;
            const float* rp = in + (rowBase + r) * 96;
            psi[t] = rp[lane];
            rr[t]  = rp[32 + lane];
            rd[t]  = rp[64 + lane];
        }
        #pragma unroll
        for (int t = 0; t < 4; t++) {
            int r = warpRow + batch * 4 + t;
            float sv, cv;
            __sincosf(psi[t], &sv, &cv);
            __half2 hxy = __floats2half2_rn(rr[t] * sv, rr[t] * cv);
            __half2 hcs = __floats2half2_rn(cv, sv);
            sXY[r * XS + lane] = *reinterpret_cast<uint32_t*>(&hxy);
            sSC[r * XS + lane] = *reinterpret_cast<uint32_t*>(&hcs);
            float rdd = ca * (0.25f * ca * (ba - rr[t]) - rd[t]);
            float* op = out + (rowBase + r) * 96;
            op[32 + lane] = rd[t];
            op[64 + lane] = rdd;
        }
    }
    __syncthreads();    // sBf + all warps' sXY/sSC visible

    // ---- MMA: warp owns 16 rows; accP = n-tiles 0..3 (P), accQ = 4..7 (Q) ----
    float accP[4][4] = {}, accQ[4][4] = {};
    const int g   = lane >> 2;
    const int tig = lane & 3;
    const int ar0 = warpRow + g;

    #pragma unroll
    for (int ks = 0; ks < 4; ks++) {
        int hj = ks * 8 + tig;
        uint32_t a0 = sXY[ar0 * XS + hj];
        uint32_t a1 = sXY[(ar0 + 8) * XS + hj];
        uint32_t a2 = sXY[ar0 * XS + hj + 4];
        uint32_t a3 = sXY[(ar0 + 8) * XS + hj + 4];
        #pragma unroll
        for (int nt = 0; nt < 4; nt++) {
            uint2 bP = sBf[nt * 128 + ks * 32 + lane];          // LDS.64
            MMA_F16(accP[nt], a0, a1, a2, a3, bP.x, bP.y);
            uint2 bQ = sBf[(nt + 4) * 128 + ks * 32 + lane];
            MMA_F16(accQ[nt], a0, a1, a2, a3, bQ.x, bQ.y);
        }
    }

    // ---- epilogue: thread owns rows (ar0, ar0+8) x cols (i0, i0+1)/ntile ----
    #pragma unroll
    for (int nt = 0; nt < 4; nt++) {
        int i0 = nt * 8 + tig * 2;
        float2 tp = *reinterpret_cast<const float2*>(&sTPV[i0]);
        #pragma unroll
        for (int rs = 0; rs < 2; rs++) {
            int r = ar0 + rs * 8;
            uint2 scu = *reinterpret_cast<const uint2*>(&sSC[r * XS + i0]);
            __half2 h0 = *reinterpret_cast<__half2*>(&scu.x);   // {c,s} col i0
            __half2 h1 = *reinterpret_cast<__half2*>(&scu.y);   // {c,s} col i0+1
            float c0 = __low2float(h0), s0 = __high2float(h0);
            float c1 = __low2float(h1), s1 = __high2float(h1);
            float P0 = accP[nt][rs * 2], P1 = accP[nt][rs * 2 + 1];
            float Q0 = accQ[nt][rs * 2], Q1 = accQ[nt][rs * 2 + 1];
            float2 pd;
            pd.x = tp.x + c0 * P0 - s0 * Q0;
            pd.y = tp.y + c1 * P1 - s1 * Q1;
            *reinterpret_cast<float2*>(&out[(rowBase + r) * 96 + i0]) = pd;
        }
    }
}

// ---------------- guarded tail kernel (R14 path; unused at 65536) -------------
__global__ void hopf_tail(const float* __restrict__ in, float* __restrict__ out,
                          int rowStart, int nrows) {
    const int tid  = threadIdx.x;
    const int lane = tid & 31;
    const int wib  = tid >> 5;

    __shared__ uint2 sABBA[1024];
    __shared__ uint4 sXYt[8][2][32];

    {
        const float4* src = reinterpret_cast<const float4*>(gABBA);
        float4*       dst = reinterpret_cast<float4*>(sABBA);
        dst[tid]       = src[tid];
        dst[tid + 256] = src[tid + 256];
    }
    const float tpv = gTPV[lane];
    const float ba  = gBA[lane];
    const float ca  = gCA[lane];
    __syncthreads();

    const int rowBase = rowStart + wib * 8;

    #pragma unroll
    for (int q = 0; q < 2; q++) {
        const int r0 = rowBase + q * 4;
        float sv[4], cv[4];
        uint4 xy;

        #pragma unroll
        for (int t = 0; t < 4; t++) {
            const int row = r0 + t;
            float psi = 0.0f, rr = 0.0f, rd = 0.0f;
            if (row < nrows) {
                const float* rp = in + (size_t)row * 96;
                psi = rp[lane];  rr = rp[32 + lane];  rd = rp[64 + lane];
            }
            __sincosf(psi, &sv[t], &cv[t]);
            reinterpret_cast<__half2*>(&xy)[t] =
                __floats2half2_rn(rr * sv[t], rr * cv[t]);
            if (row < nrows) {
                float rdd = ca * (0.25f * ca * (ba - rr) - rd);
                float* op = out + (size_t)row * 96;
                op[32 + lane] = rd;
                op[64 + lane] = rdd;
            }
        }

        sXYt[wib][q][lane] = xy;
        __syncwarp();

        __half2 z = __floats2half2_rn(0.0f, 0.0f);
        __half2 aP0[4] = {z,z,z,z}, aP1[4] = {z,z,z,z};
        __half2 aQ0[4] = {z,z,z,z}, aQ1[4] = {z,z,z,z};

        #pragma unroll
        for (int j = 0; j < 16; j++) {
            uint2 m = sABBA[j * 32 + lane];
            __half2 ab  = *reinterpret_cast<__half2*>(&m.x);
            __half2 ba2 = *reinterpret_cast<__half2*>(&m.y);
            uint4 pxy = sXYt[wib][q][j];
            const __half2* hx = reinterpret_cast<const __half2*>(&pxy);
            #pragma unroll
            for (int t = 0; t < 4; t++) {
                aP0[t] = __hfma2(ab,  hx[t], aP0[t]);
                aQ0[t] = __hfma2(ba2, hx[t], aQ0[t]);
            }
        }
        #pragma unroll
        for (int j = 16; j < 32; j++) {
            uint2 m = sABBA[j * 32 + lane];
            __half2 ab  = *reinterpret_cast<__half2*>(&m.x);
            __half2 ba2 = *reinterpret_cast<__half2*>(&m.y);
            uint4 pxy = sXYt[wib][q][j];
            const __half2* hx = reinterpret_cast<const __half2*>(&pxy);
            #pragma unroll
            for (int t = 0; t < 4; t++) {
                aP1[t] = __hfma2(ab,  hx[t], aP1[t]);
                aQ1[t] = __hfma2(ba2, hx[t], aQ1[t]);
            }
        }

        #pragma unroll
        for (int t = 0; t < 4; t++) {
            const int row = r0 + t;
            if (row < nrows) {
                float2 p0 = __half22float2(aP0[t]);
                float2 p1 = __half22float2(aP1[t]);
                float2 q0 = __half22float2(aQ0[t]);
                float2 q1 = __half22float2(aQ1[t]);
                float P = (p0.x + p1.x) - (p0.y + p1.y);
                float Q = (q0.x + q1.x) + (q0.y + q1.y);
                out[(size_t)row * 96 + lane] = tpv + cv[t] * P - sv[t] * Q;
            }
        }
    }
}

extern "C" void kernel_launch(void* const* d_in, const int* in_sizes, int n_in,
                              void* d_out, int out_size) {
    const float* states = (const float*)d_in[0];
    const float* v      = (const float*)d_in[1];
    const float* b      = (const float*)d_in[2];
    const float* c      = (const float*)d_in[3];
    const float* w      = (const float*)d_in[4];
    const float* phi    = (const float*)d_in[5];
    float* out = (float*)d_out;

    const int nrows = in_sizes[0] / 96;         // 65536
    prep_kernel<<<1, 1024>>>(v, b, c, w, phi);

    const int fullBlocks = nrows / 64;          // 64 rows per 128-thread CTA
    if (fullBlocks > 0)
        hopf_kernel<<<fullBlocks, 128>>>(states, out);

    const int covered = fullBlocks * 64;
    if (covered < nrows)
        hopf_tail<<<1, 256>>>(states, out, covered, nrows);
}